// round 17
// baseline (speedup 1.0000x reference)
#include <cuda_runtime.h>
#include <cuda_fp16.h>
#include <cstdint>

#define T_TOK 4096
#define D_IN  2048
#define D_MOE 768
#define TWO_DM 1536

// ---- tiling: 128M x 256N, 8 warps (2 wm x 4 wn) of 64x64, 1 CTA/SM ----
#define BM 128
#define BN 256
#define BK 64                       // halves per K chunk = 128B swizzled row
#define A_BYTES  (BM * 128)         // 16 KB
#define B_BYTES  (BN * 128)         // 32 KB
#define STAGE_BYTES (A_BYTES + B_BYTES)   // 48 KB
#define S_STAGES 3
#define SMEM_TOTAL (S_STAGES * STAGE_BYTES)   // 144 KB -> 1 CTA/SM

#define G1_PER_BM 6                 // h cols: 6 x 128
#define G2_PER_BM 8                 // out cols: 8 x 256

// Scratch (device globals: allocation-free per harness rules)
__device__ __align__(16) __half g_xh[T_TOK * D_IN];
__device__ __align__(16) __half g_guw[TWO_DM * D_IN];
__device__ __align__(16) __half g_dw[D_IN * D_MOE];
__device__ __align__(16) __half g_h[T_TOK * D_MOE];
__device__ unsigned int g_ready[32];   // per 128-row block of h: finished G1 tiles (of 6)

// ---------------------------------------------------------------------------
// PTX helpers (non-'a' features only: cp.async, ldmatrix, mma.sync, griddepcontrol)
// ---------------------------------------------------------------------------
__device__ __forceinline__ uint32_t smem_u32(const void* p) {
    uint32_t a;
    asm("{ .reg .u64 t; cvta.to.shared.u64 t, %1; cvt.u32.u64 %0, t; }" : "=r"(a) : "l"(p));
    return a;
}
__device__ __forceinline__ void cp16(uint32_t saddr, const void* gaddr) {
    asm volatile("cp.async.cg.shared.global [%0], [%1], 16;" :: "r"(saddr), "l"(gaddr));
}
#define CP_COMMIT() asm volatile("cp.async.commit_group;" ::: "memory")
#define CP_WAIT(n)  asm volatile("cp.async.wait_group %0;" :: "n"(n) : "memory")

__device__ __forceinline__ void ldsm_x4(uint32_t& r0, uint32_t& r1, uint32_t& r2, uint32_t& r3,
                                        uint32_t addr) {
    asm volatile("ldmatrix.sync.aligned.m8n8.x4.shared.b16 {%0,%1,%2,%3}, [%4];"
                 : "=r"(r0), "=r"(r1), "=r"(r2), "=r"(r3) : "r"(addr));
}
__device__ __forceinline__ void mma_16816(float* c, const uint32_t* a, const uint32_t* b) {
    asm volatile(
        "mma.sync.aligned.m16n8k16.row.col.f32.f16.f16.f32 "
        "{%0,%1,%2,%3}, {%4,%5,%6,%7}, {%8,%9}, {%0,%1,%2,%3};"
        : "+f"(c[0]), "+f"(c[1]), "+f"(c[2]), "+f"(c[3])
        : "r"(a[0]), "r"(a[1]), "r"(a[2]), "r"(a[3]), "r"(b[0]), "r"(b[1]));
}
__device__ __forceinline__ void st_cs_f2(float* p, float a, float b) {
    asm volatile("st.global.cs.v2.f32 [%0], {%1, %2};" :: "l"(p), "f"(a), "f"(b) : "memory");
}
__device__ __forceinline__ float silu_f(float v) { return v / (1.0f + __expf(-v)); }

// ---------------------------------------------------------------------------
// fp32 -> fp16 conversion (R15 bulk form) + ready-flag reset.
// ---------------------------------------------------------------------------
__global__ void convert_kernel(const float* __restrict__ x,
                               const float* __restrict__ gup,
                               const float* __restrict__ dp,
                               const int* __restrict__ eidx) {
    if (blockIdx.x == 0 && threadIdx.x < 32) g_ready[threadIdx.x] = 0;
    const int e = *eidx;
    const float4* gu4 = (const float4*)(gup + (size_t)e * TWO_DM * D_IN);
    const float4* dw4 = (const float4*)(dp + (size_t)e * D_IN * D_MOE);
    const float4* x4 = (const float4*)x;
    uint4* xo = (uint4*)g_xh;
    uint4* go = (uint4*)g_guw;
    uint4* do_ = (uint4*)g_dw;
    const int stride = gridDim.x * blockDim.x;
    const int tid = blockIdx.x * blockDim.x + threadIdx.x;

    auto pack2 = [](float a, float b) {
        __half2 h = __floats2half2_rn(a, b);
        return *(uint32_t*)&h;
    };
    const int nx = T_TOK * D_IN / 8;
    for (int i = tid; i < nx; i += stride) {
        float4 v0 = x4[2 * i], v1 = x4[2 * i + 1];
        xo[i] = make_uint4(pack2(v0.x, v0.y), pack2(v0.z, v0.w),
                           pack2(v1.x, v1.y), pack2(v1.z, v1.w));
    }
    const int ng = TWO_DM * D_IN / 8;
    for (int i = tid; i < ng; i += stride) {
        float4 v0 = gu4[2 * i], v1 = gu4[2 * i + 1];
        go[i] = make_uint4(pack2(v0.x, v0.y), pack2(v0.z, v0.w),
                           pack2(v1.x, v1.y), pack2(v1.z, v1.w));
    }
    const int nd = D_IN * D_MOE / 8;
    for (int i = tid; i < nd; i += stride) {
        float4 v0 = dw4[2 * i], v1 = dw4[2 * i + 1];
        do_[i] = make_uint4(pack2(v0.x, v0.y), pack2(v0.z, v0.w),
                            pack2(v1.x, v1.y), pack2(v1.z, v1.w));
    }
}

// ---------------------------------------------------------------------------
// 128x256 HMMA GEMM, 1 CTA/SM, 256 threads = 8 warps (2 wm x 4 wn), 64x64/warp.
// B smem rows (256):
//   G1: 32-row groups; group g: wn=g>>1, (g&1)? up : gate rows for h-cols
//       [bn*128 + wn*32, +32). Warp wn's 64 rows = 32 gate + 32 up, same cols.
//   G2: contiguous down_w rows (out cols bn*256 + row).
// G1 publishes g_ready[bm] (6 tiles per bm); G2 is PDL-launched and gates on it.
// ---------------------------------------------------------------------------
template <int KDIM, int NCHUNK, bool IS_G1>
__global__ __launch_bounds__(256, 1) void gemm_hmma(float* __restrict__ out) {
    extern __shared__ char smem[];
    const uint32_t sbase = smem_u32(smem);
    const int tid = threadIdx.x, wid = tid >> 5, lane = tid & 31;
    const int wm = wid & 1, wn = wid >> 1;         // 2 x 4 warp grid
    const int g = lane >> 2, q = lane & 3;
    const int bn = blockIdx.x, bm = blockIdx.y;

    if (IS_G1) {
        asm volatile("griddepcontrol.launch_dependents;");
    } else {
        if (tid == 0) {
            while (atomicAdd(&g_ready[bm], 0u) < G1_PER_BM) __nanosleep(64);
        }
        __syncthreads();
        __threadfence();   // acquire ordering for g_h reads
    }

    const __half *Ap, *Bg, *Bu, *Bd;
    if (IS_G1) {
        Ap = g_xh + (size_t)bm * BM * KDIM;
        Bg = g_guw + (size_t)(bn * 128) * KDIM;           // gate rows
        Bu = g_guw + (size_t)(D_MOE + bn * 128) * KDIM;   // up rows
        Bd = nullptr;
    } else {
        Ap = g_h + (size_t)bm * BM * KDIM;
        Bd = g_dw + (size_t)(bn * 256) * KDIM;
        Bg = Bu = nullptr;
    }

    // stage loader: A 1024 granules (4/thr), B 2048 granules (8/thr), 16B each
    auto load_stage = [&](int stage, int chunk) {
        const uint32_t sA = sbase + stage * STAGE_BYTES;
        const uint32_t sB = sA + A_BYTES;
        const int k0 = chunk * BK;
#pragma unroll
        for (int i = 0; i < 4; i++) {
            int gi = tid + i * 256;
            int r = gi >> 3, c = gi & 7;
            cp16(sA + r * 128 + ((c ^ (r & 7)) << 4), Ap + (size_t)r * KDIM + k0 + c * 8);
        }
#pragma unroll
        for (int i = 0; i < 8; i++) {
            int gi = tid + i * 256;
            int r = gi >> 3, c = gi & 7;
            const __half* src;
            if (IS_G1) {
                int grp = r >> 5, w = r & 31;
                int hrow = (grp >> 1) * 32 + w;
                src = ((grp & 1) ? Bu : Bg) + (size_t)hrow * KDIM;
            } else {
                src = Bd + (size_t)r * KDIM;
            }
            cp16(sB + r * 128 + ((c ^ (r & 7)) << 4), src + k0 + c * 8);
        }
        CP_COMMIT();
    };

    const int r7 = lane & 7;
    const int laneRowA = ((lane >> 3) & 1) * 8 + r7;
    const int kselA = lane >> 4;
    const int laneRowB = (lane >> 4) * 8 + r7;
    const int kselB = (lane >> 3) & 1;

    float acc[4][8][4];
#pragma unroll
    for (int a = 0; a < 4; a++)
#pragma unroll
        for (int b = 0; b < 8; b++)
#pragma unroll
            for (int c = 0; c < 4; c++) acc[a][b][c] = 0.f;

    load_stage(0, 0);
    load_stage(1, 1);

    for (int j = 0; j < NCHUNK; j++) {
        if (j == NCHUNK - 1) { CP_WAIT(0); } else { CP_WAIT(1); }
        __syncthreads();
        if (j + 2 < NCHUNK) load_stage((j + 2) % S_STAGES, j + 2);

        const uint32_t sA = sbase + (j % S_STAGES) * STAGE_BYTES;
        const uint32_t sB = sA + A_BYTES;

#pragma unroll
        for (int kk = 0; kk < 4; kk++) {
            uint32_t a[4][4];
#pragma unroll
            for (int mt = 0; mt < 4; mt++) {
                int row = wm * 64 + mt * 16 + laneRowA;
                uint32_t addr = sA + row * 128 + (((kk * 2 + kselA) ^ r7) << 4);
                ldsm_x4(a[mt][0], a[mt][1], a[mt][2], a[mt][3], addr);
            }
            uint32_t b[8][2];
#pragma unroll
            for (int p = 0; p < 4; p++) {
                int row = wn * 64 + p * 16 + laneRowB;
                uint32_t addr = sB + row * 128 + (((kk * 2 + kselB) ^ r7) << 4);
                ldsm_x4(b[2 * p][0], b[2 * p][1], b[2 * p + 1][0], b[2 * p + 1][1], addr);
            }
#pragma unroll
            for (int mt = 0; mt < 4; mt++)
#pragma unroll
                for (int ni = 0; ni < 8; ni++)
                    mma_16816(acc[mt][ni], a[mt], b[ni]);
        }
    }

    if (IS_G1) {
        // warp's B rows: p0,p1 (ni 0..3) = gate; p2,p3 (ni 4..7) = up, same h cols
#pragma unroll
        for (int mt = 0; mt < 4; mt++)
#pragma unroll
            for (int ni = 0; ni < 4; ni++) {
                int row = bm * BM + wm * 64 + mt * 16 + g;
                int col = bn * 128 + wn * 32 + ni * 8 + q * 2;
                float* cg = acc[mt][ni];
                float* cu = acc[mt][ni + 4];
                __half2 h01 = __floats2half2_rn(silu_f(cg[0]) * cu[0], silu_f(cg[1]) * cu[1]);
                __half2 h23 = __floats2half2_rn(silu_f(cg[2]) * cu[2], silu_f(cg[3]) * cu[3]);
                *(__half2*)&g_h[(size_t)row * D_MOE + col] = h01;
                *(__half2*)&g_h[(size_t)(row + 8) * D_MOE + col] = h23;
            }
        __threadfence();
        __syncthreads();
        if (tid == 0) atomicAdd(&g_ready[bm], 1u);
    } else {
#pragma unroll
        for (int mt = 0; mt < 4; mt++)
#pragma unroll
            for (int ni = 0; ni < 8; ni++) {
                int row = bm * BM + wm * 64 + mt * 16 + g;
                int col = bn * 256 + wn * 64 + ni * 8 + q * 2;
                float* c = acc[mt][ni];
                st_cs_f2(&out[(size_t)row * D_IN + col], c[0], c[1]);
                st_cs_f2(&out[(size_t)(row + 8) * D_IN + col], c[2], c[3]);
            }
    }
}

// ---------------------------------------------------------------------------
extern "C" void kernel_launch(void* const* d_in, const int* in_sizes, int n_in,
                              void* d_out, int out_size) {
    const float* x = (const float*)d_in[0];
    const float* gup = (const float*)d_in[1];
    const float* dp = (const float*)d_in[2];
    const int* eidx = (const int*)d_in[3];
    float* out = (float*)d_out;

    cudaFuncSetAttribute(gemm_hmma<D_IN, D_IN / BK, true>,
                         cudaFuncAttributeMaxDynamicSharedMemorySize, SMEM_TOTAL);
    cudaFuncSetAttribute(gemm_hmma<D_MOE, D_MOE / BK, false>,
                         cudaFuncAttributeMaxDynamicSharedMemorySize, SMEM_TOTAL);

    convert_kernel<<<2048, 256>>>(x, gup, dp, eidx);

    // G1: normal launch (full dependency on convert), bm-major completion
    gemm_hmma<D_IN, D_IN / BK, true><<<dim3(G1_PER_BM, 32), 256, SMEM_TOTAL>>>(nullptr);

    // G2: PDL — CTAs dispatch behind G1's tail, gate on g_ready[bm]
    {
        cudaLaunchConfig_t cfg = {};
        cfg.gridDim = dim3(G2_PER_BM, 32);
        cfg.blockDim = dim3(256);
        cfg.dynamicSmemBytes = SMEM_TOTAL;
        cfg.stream = 0;
        cudaLaunchAttribute attr[1];
        attr[0].id = cudaLaunchAttributeProgrammaticStreamSerialization;
        attr[0].val.programmaticStreamSerializationAllowed = 1;
        cfg.attrs = attr;
        cfg.numAttrs = 1;
        cudaLaunchKernelEx(&cfg, gemm_hmma<D_MOE, D_MOE / BK, false>, out);
    }
}